// round 1
// baseline (speedup 1.0000x reference)
#include <cuda_runtime.h>
#include <math.h>

// Problem constants
#define T_   256
#define B_   128
#define F_   1024
#define U_   512
#define G4_  2048   // 4*U
#define CODES_ 1024
#define ROWS_ 32768 // T*B

// ---------------------------------------------------------------------------
// Scratch (static device globals; no allocation at runtime)
// ---------------------------------------------------------------------------
__device__ float g_xz   [(size_t)ROWS_ * G4_];   // 268 MB: input projections, gate-reordered
__device__ float g_hseq [(size_t)ROWS_ * U_];    // 67 MB:  h_t for all t
__device__ float g_h0   [B_ * U_];               // zero initial h
__device__ float g_c    [B_ * U_];               // cell state (in-place)
__device__ float g_Win4 [(size_t)F_ * G4_];      // W_in, columns reordered to u*4+gate
__device__ float g_Wrec4[(size_t)U_ * G4_];      // W_rec, same reorder
__device__ float g_b4   [G4_];                   // b_lstm, same reorder

// ---------------------------------------------------------------------------
// Weight reorder: new col = u*4 + gate  <-  old col = gate*U + u
// (gate order i,f,g,o as in the reference split)
// ---------------------------------------------------------------------------
__global__ void reorder_gates(const float* __restrict__ W, float* __restrict__ W4, int total) {
    int idx = blockIdx.x * blockDim.x + threadIdx.x;
    if (idx >= total) return;
    int col = idx & (G4_ - 1);
    int k   = idx >> 11;           // G4_ = 2048 = 2^11
    int u   = col >> 2;
    int g   = col & 3;
    W4[idx] = W[(size_t)k * G4_ + g * U_ + u];
}

__global__ void init_kernel(const float* __restrict__ b_lstm,
                            float* __restrict__ b4,
                            float* __restrict__ h0,
                            float* __restrict__ c) {
    int idx = blockIdx.x * blockDim.x + threadIdx.x;
    if (idx < G4_) b4[idx] = b_lstm[(idx & 3) * U_ + (idx >> 2)];
    if (idx < B_ * U_) { h0[idx] = 0.0f; c[idx] = 0.0f; }
}

// ---------------------------------------------------------------------------
// Generic fp32 SGEMM: C[M,N] = op(A[M,K] * rowscale) @ B[K,N] + bias, optional relu
// 128x128 block tile, K-chunk 8, 256 threads, 8x8 per-thread microtile.
// M % 128 == 0, N % 128 == 0, K % 8 == 0 (holds for all uses here).
// mask: optional per-row scale (length M), may be nullptr.
// ---------------------------------------------------------------------------
__global__ __launch_bounds__(256) void sgemm128(
    const float* __restrict__ A, const float* __restrict__ Bm,
    const float* __restrict__ bias, const float* __restrict__ mask,
    float* __restrict__ C, int M, int N, int K, int relu)
{
    __shared__ float As[8][128];
    __shared__ float Bs[8][128];

    int tid = threadIdx.x;
    int m0 = blockIdx.y * 128;
    int n0 = blockIdx.x * 128;
    int tx = tid & 15;          // 16 column groups of 8
    int ty = tid >> 4;          // 16 row groups of 8

    // A tile loader: 128 rows x 8 k, one float4 per thread
    int arow = tid >> 1;
    int ak   = (tid & 1) * 4;
    const float* Aptr = A + (size_t)(m0 + arow) * K + ak;
    float amul = mask ? mask[m0 + arow] : 1.0f;

    // B tile loader: 8 k-rows x 128 cols, one float4 per thread
    int brow = tid >> 5;
    int bcol = (tid & 31) * 4;
    const float* Bptr = Bm + (size_t)brow * N + n0 + bcol;

    float acc[8][8];
    #pragma unroll
    for (int i = 0; i < 8; i++)
        #pragma unroll
        for (int j = 0; j < 8; j++) acc[i][j] = 0.0f;

    for (int k0 = 0; k0 < K; k0 += 8) {
        float4 av = *(const float4*)(Aptr + k0);
        As[ak + 0][arow] = av.x * amul;
        As[ak + 1][arow] = av.y * amul;
        As[ak + 2][arow] = av.z * amul;
        As[ak + 3][arow] = av.w * amul;
        *(float4*)&Bs[brow][bcol] = *(const float4*)(Bptr + (size_t)k0 * N);
        __syncthreads();

        #pragma unroll
        for (int kk = 0; kk < 8; kk++) {
            float a[8], b[8];
            *(float4*)(a)     = *(float4*)&As[kk][ty * 8];
            *(float4*)(a + 4) = *(float4*)&As[kk][ty * 8 + 4];
            *(float4*)(b)     = *(float4*)&Bs[kk][tx * 8];
            *(float4*)(b + 4) = *(float4*)&Bs[kk][tx * 8 + 4];
            #pragma unroll
            for (int i = 0; i < 8; i++)
                #pragma unroll
                for (int j = 0; j < 8; j++)
                    acc[i][j] += a[i] * b[j];
        }
        __syncthreads();
    }

    #pragma unroll
    for (int i = 0; i < 8; i++) {
        int r = m0 + ty * 8 + i;
        float* Cp = C + (size_t)r * N + n0 + tx * 8;
        float4 v0, v1;
        v0.x = acc[i][0] + bias[n0 + tx * 8 + 0];
        v0.y = acc[i][1] + bias[n0 + tx * 8 + 1];
        v0.z = acc[i][2] + bias[n0 + tx * 8 + 2];
        v0.w = acc[i][3] + bias[n0 + tx * 8 + 3];
        v1.x = acc[i][4] + bias[n0 + tx * 8 + 4];
        v1.y = acc[i][5] + bias[n0 + tx * 8 + 5];
        v1.z = acc[i][6] + bias[n0 + tx * 8 + 6];
        v1.w = acc[i][7] + bias[n0 + tx * 8 + 7];
        if (relu) {
            v0.x = fmaxf(v0.x, 0.f); v0.y = fmaxf(v0.y, 0.f);
            v0.z = fmaxf(v0.z, 0.f); v0.w = fmaxf(v0.w, 0.f);
            v1.x = fmaxf(v1.x, 0.f); v1.y = fmaxf(v1.y, 0.f);
            v1.z = fmaxf(v1.z, 0.f); v1.w = fmaxf(v1.w, 0.f);
        }
        *(float4*)(Cp)     = v0;
        *(float4*)(Cp + 4) = v1;
    }
}

// ---------------------------------------------------------------------------
// One LSTM timestep, fused: z = xz_t + h_prev @ Wrec4; gates; c,h update.
// Block tile: 32 batches x 128 gate-cols (= 32 units). Grid (16, 4).
// 256 threads; each computes a 4x4 microtile whose 4 columns are exactly the
// (i,f,g,o) gates of ONE unit -> activation + state update is thread-local.
// ---------------------------------------------------------------------------
__global__ __launch_bounds__(256) void lstm_step(
    const float* __restrict__ hprev,  // [B_][U_]  (= h_seq[t-1] or zeros)
    const float* __restrict__ xz,     // [B_][G4_] for this t (gate-reordered)
    const float* __restrict__ Wrec,   // [U_][G4_] gate-reordered
    float* __restrict__ c,            // [B_][U_]  in-place
    float* __restrict__ hout)         // [B_][U_]  (= h_seq[t])
{
    __shared__ float As[8][32];
    __shared__ float Bs[8][128];

    int tid = threadIdx.x;
    int n0 = blockIdx.x * 128;   // gate-col tile
    int b0 = blockIdx.y * 32;    // batch tile
    int tx = tid & 31;           // unit within tile
    int ty = tid >> 5;           // batch group of 4

    int arow = tid >> 1;         // 0..127 but only tid<64 loads (32 rows x 2 halves)
    int ak   = (tid & 1) * 4;

    float acc[4][4];
    #pragma unroll
    for (int i = 0; i < 4; i++)
        #pragma unroll
        for (int j = 0; j < 4; j++) acc[i][j] = 0.0f;

    for (int k0 = 0; k0 < U_; k0 += 8) {
        if (tid < 64) {
            float4 av = *(const float4*)(hprev + (size_t)(b0 + arow) * U_ + k0 + ak);
            As[ak + 0][arow] = av.x;
            As[ak + 1][arow] = av.y;
            As[ak + 2][arow] = av.z;
            As[ak + 3][arow] = av.w;
        }
        *(float4*)&Bs[ty][tx * 4] =
            *(const float4*)(Wrec + (size_t)(k0 + ty) * G4_ + n0 + tx * 4);
        __syncthreads();

        #pragma unroll
        for (int kk = 0; kk < 8; kk++) {
            float b[4];
            *(float4*)b = *(float4*)&Bs[kk][tx * 4];
            #pragma unroll
            for (int i = 0; i < 4; i++) {
                float a = As[kk][ty * 4 + i];
                acc[i][0] += a * b[0];
                acc[i][1] += a * b[1];
                acc[i][2] += a * b[2];
                acc[i][3] += a * b[3];
            }
        }
        __syncthreads();
    }

    int u = (n0 >> 2) + tx;   // global unit index
    #pragma unroll
    for (int i = 0; i < 4; i++) {
        int b = b0 + ty * 4 + i;
        const float* xzp = xz + (size_t)b * G4_ + n0 + tx * 4;
        float zi = acc[i][0] + xzp[0];
        float zf = acc[i][1] + xzp[1];
        float zg = acc[i][2] + xzp[2];
        float zo = acc[i][3] + xzp[3];
        float ig = 1.0f / (1.0f + expf(-zi));
        float fg = 1.0f / (1.0f + expf(-zf));
        float gg = tanhf(zg);
        float og = 1.0f / (1.0f + expf(-zo));
        size_t sidx = (size_t)b * U_ + u;
        float cn = fg * c[sidx] + ig * gg;
        c[sidx] = cn;
        hout[sidx] = og * tanhf(cn);
    }
}

// ---------------------------------------------------------------------------
// In-place row softmax over rows of length CODES_ (1024). One block per row.
// ---------------------------------------------------------------------------
__global__ __launch_bounds__(256) void softmax_kernel(float* __restrict__ out) {
    __shared__ float red[8];
    int tid = threadIdx.x;
    float* p = out + (size_t)blockIdx.x * CODES_;

    float4 v = *(float4*)(p + tid * 4);
    float m = fmaxf(fmaxf(v.x, v.y), fmaxf(v.z, v.w));
    #pragma unroll
    for (int o = 16; o > 0; o >>= 1) m = fmaxf(m, __shfl_xor_sync(0xFFFFFFFFu, m, o));
    if ((tid & 31) == 0) red[tid >> 5] = m;
    __syncthreads();
    float bm = red[0];
    #pragma unroll
    for (int i = 1; i < 8; i++) bm = fmaxf(bm, red[i]);
    __syncthreads();

    v.x = expf(v.x - bm); v.y = expf(v.y - bm);
    v.z = expf(v.z - bm); v.w = expf(v.w - bm);
    float s = v.x + v.y + v.z + v.w;
    #pragma unroll
    for (int o = 16; o > 0; o >>= 1) s += __shfl_xor_sync(0xFFFFFFFFu, s, o);
    if ((tid & 31) == 0) red[tid >> 5] = s;
    __syncthreads();
    float bs = red[0];
    #pragma unroll
    for (int i = 1; i < 8; i++) bs += red[i];
    float inv = 1.0f / bs;
    v.x *= inv; v.y *= inv; v.z *= inv; v.w *= inv;
    *(float4*)(p + tid * 4) = v;
}

// ---------------------------------------------------------------------------
// Launch
// ---------------------------------------------------------------------------
extern "C" void kernel_launch(void* const* d_in, const int* in_sizes, int n_in,
                              void* d_out, int out_size) {
    const float* x       = (const float*)d_in[0];   // [T,B,F]
    const float* mask    = (const float*)d_in[1];   // [T,B]
    const float* W_in    = (const float*)d_in[2];   // [F,4U]
    const float* W_rec   = (const float*)d_in[3];   // [U,4U]
    const float* b_lstm  = (const float*)d_in[4];   // [4U]
    const float* W_dense = (const float*)d_in[5];   // [U,CODES]
    const float* b_dense = (const float*)d_in[6];   // [CODES]
    float* out = (float*)d_out;                     // [T,B,CODES]

    float *xz, *hseq, *h0, *c, *Win4, *Wrec4, *b4;
    cudaGetSymbolAddress((void**)&xz,    g_xz);
    cudaGetSymbolAddress((void**)&hseq,  g_hseq);
    cudaGetSymbolAddress((void**)&h0,    g_h0);
    cudaGetSymbolAddress((void**)&c,     g_c);
    cudaGetSymbolAddress((void**)&Win4,  g_Win4);
    cudaGetSymbolAddress((void**)&Wrec4, g_Wrec4);
    cudaGetSymbolAddress((void**)&b4,    g_b4);

    // Prep: gate-reorder weights/bias, zero h0/c
    reorder_gates<<<(F_ * G4_ + 255) / 256, 256>>>(W_in,  Win4,  F_ * G4_);
    reorder_gates<<<(U_ * G4_ + 255) / 256, 256>>>(W_rec, Wrec4, U_ * G4_);
    init_kernel<<<(B_ * U_ + 255) / 256, 256>>>(b_lstm, b4, h0, c);

    // Phase 1: xz = x @ Win4 + b4   (M=32768, N=2048, K=1024)
    sgemm128<<<dim3(G4_ / 128, ROWS_ / 128), 256>>>(
        x, Win4, b4, nullptr, xz, ROWS_, G4_, F_, 0);

    // Phase 2: recurrence (h_seq acts as its own double buffer)
    for (int t = 0; t < T_; t++) {
        const float* hp = t ? (hseq + (size_t)(t - 1) * B_ * U_) : h0;
        lstm_step<<<dim3(G4_ / 128, B_ / 32), 256>>>(
            hp, xz + (size_t)t * B_ * G4_, Wrec4, c, hseq + (size_t)t * B_ * U_);
    }

    // Phase 3: logits = relu((h_seq * mask) @ W_dense + b_dense) -> d_out
    sgemm128<<<dim3(CODES_ / 128, ROWS_ / 128), 256>>>(
        hseq, W_dense, b_dense, mask, out, ROWS_, CODES_, U_, 1);

    // Phase 4: in-place row softmax
    softmax_kernel<<<ROWS_, 256>>>(out);
}

// round 3
// speedup vs baseline: 1.4701x; 1.4701x over previous
#include <cuda_runtime.h>
#include <math.h>

// Problem constants
#define T_   256
#define B_   128
#define F_   1024
#define U_   512
#define G4_  2048   // 4*U
#define CODES_ 1024
#define ROWS_ 32768 // T*B

#define RBLK 128    // persistent recurrence blocks (all co-resident, <=148 SMs)
#define KC   32     // recurrence K chunk

// ---------------------------------------------------------------------------
// Scratch (static device globals; no allocation at runtime)
// ---------------------------------------------------------------------------
__device__ float g_xz   [(size_t)ROWS_ * G4_];   // input projections, gate-reordered
__device__ float g_hseq [(size_t)ROWS_ * U_];    // h_t for all t
__device__ float g_h0   [B_ * U_];               // zero initial h
__device__ float g_Win4 [(size_t)F_ * G4_];      // W_in,  cols reordered to u*4+gate
__device__ float g_Wrec4[(size_t)U_ * G4_];      // W_rec, same reorder
__device__ float g_b4   [G4_];                   // b_lstm, same reorder
__device__ unsigned g_bar;                       // grid barrier counter

// ---------------------------------------------------------------------------
// Weight reorder: new col = u*4 + gate  <-  old col = gate*U + u
// ---------------------------------------------------------------------------
__global__ void reorder_gates(const float* __restrict__ W, float* __restrict__ W4, int total) {
    int idx = blockIdx.x * blockDim.x + threadIdx.x;
    if (idx >= total) return;
    int col = idx & (G4_ - 1);
    int k   = idx >> 11;
    int u   = col >> 2;
    int g   = col & 3;
    W4[idx] = W[(size_t)k * G4_ + g * U_ + u];
}

__global__ void init_kernel(const float* __restrict__ b_lstm,
                            float* __restrict__ b4,
                            float* __restrict__ h0,
                            unsigned* __restrict__ bar) {
    int idx = blockIdx.x * blockDim.x + threadIdx.x;
    if (idx == 0) *bar = 0u;
    if (idx < G4_) b4[idx] = b_lstm[(idx & 3) * U_ + (idx >> 2)];
    if (idx < B_ * U_) h0[idx] = 0.0f;
}

// ---------------------------------------------------------------------------
// fp32 SGEMM: C[M,N] = (A[M,K] * rowscale) @ B[K,N] + bias, optional relu
// 128x128 tile, K-chunk 8, 256 threads, 8x8 microtile, register prefetch.
// ---------------------------------------------------------------------------
__global__ __launch_bounds__(256) void sgemm128(
    const float* __restrict__ A, const float* __restrict__ Bm,
    const float* __restrict__ bias, const float* __restrict__ mask,
    float* __restrict__ C, int M, int N, int K, int relu)
{
    __shared__ float As[8][128];
    __shared__ float Bs[8][128];

    int tid = threadIdx.x;
    int m0 = blockIdx.y * 128;
    int n0 = blockIdx.x * 128;
    int tx = tid & 15;
    int ty = tid >> 4;

    int arow = tid >> 1;
    int ak   = (tid & 1) * 4;
    const float* Aptr = A + (size_t)(m0 + arow) * K + ak;
    float amul = mask ? mask[m0 + arow] : 1.0f;

    int brow = tid >> 5;
    int bcol = (tid & 31) * 4;
    const float* Bptr = Bm + (size_t)brow * N + n0 + bcol;

    float acc[8][8];
    #pragma unroll
    for (int i = 0; i < 8; i++)
        #pragma unroll
        for (int j = 0; j < 8; j++) acc[i][j] = 0.0f;

    float4 aNext = *(const float4*)(Aptr);
    float4 bNext = *(const float4*)(Bptr);

    for (int k0 = 0; k0 < K; k0 += 8) {
        As[ak + 0][arow] = aNext.x * amul;
        As[ak + 1][arow] = aNext.y * amul;
        As[ak + 2][arow] = aNext.z * amul;
        As[ak + 3][arow] = aNext.w * amul;
        *(float4*)&Bs[brow][bcol] = bNext;
        __syncthreads();

        if (k0 + 8 < K) {   // prefetch next tile during compute
            aNext = *(const float4*)(Aptr + k0 + 8);
            bNext = *(const float4*)(Bptr + (size_t)(k0 + 8) * N);
        }

        #pragma unroll
        for (int kk = 0; kk < 8; kk++) {
            float a[8], b[8];
            *(float4*)(a)     = *(float4*)&As[kk][ty * 8];
            *(float4*)(a + 4) = *(float4*)&As[kk][ty * 8 + 4];
            *(float4*)(b)     = *(float4*)&Bs[kk][tx * 8];
            *(float4*)(b + 4) = *(float4*)&Bs[kk][tx * 8 + 4];
            #pragma unroll
            for (int i = 0; i < 8; i++)
                #pragma unroll
                for (int j = 0; j < 8; j++)
                    acc[i][j] += a[i] * b[j];
        }
        __syncthreads();
    }

    #pragma unroll
    for (int i = 0; i < 8; i++) {
        int r = m0 + ty * 8 + i;
        float* Cp = C + (size_t)r * N + n0 + tx * 8;
        float4 v0, v1;
        v0.x = acc[i][0] + bias[n0 + tx * 8 + 0];
        v0.y = acc[i][1] + bias[n0 + tx * 8 + 1];
        v0.z = acc[i][2] + bias[n0 + tx * 8 + 2];
        v0.w = acc[i][3] + bias[n0 + tx * 8 + 3];
        v1.x = acc[i][4] + bias[n0 + tx * 8 + 4];
        v1.y = acc[i][5] + bias[n0 + tx * 8 + 5];
        v1.z = acc[i][6] + bias[n0 + tx * 8 + 6];
        v1.w = acc[i][7] + bias[n0 + tx * 8 + 7];
        if (relu) {
            v0.x = fmaxf(v0.x, 0.f); v0.y = fmaxf(v0.y, 0.f);
            v0.z = fmaxf(v0.z, 0.f); v0.w = fmaxf(v0.w, 0.f);
            v1.x = fmaxf(v1.x, 0.f); v1.y = fmaxf(v1.y, 0.f);
            v1.z = fmaxf(v1.z, 0.f); v1.w = fmaxf(v1.w, 0.f);
        }
        *(float4*)(Cp)     = v0;
        *(float4*)(Cp + 4) = v1;
    }
}

// ---------------------------------------------------------------------------
// Persistent LSTM recurrence: ONE launch for all 256 steps.
// 128 blocks x 256 threads. Block j owns gate-cols [j*16, j*16+16) = units
// [j*4, j*4+4). Each thread owns a 2(batch) x 4(gate) microtile = 2 (b,u)
// state cells, whose c values live in REGISTERS for the whole sequence.
// W_rec slice (512x16, 32KB) cached in SMEM once. h staged per K-chunk in
// SMEM via __ldcg (L2-coherent; h[t] is produced by OTHER blocks).
// Software grid barrier per step (monotonic counter, reset by init_kernel).
// ---------------------------------------------------------------------------
__global__ __launch_bounds__(256) void lstm_persistent(
    const float* __restrict__ h0,
    const float* __restrict__ xz,     // [T][B][G4]
    const float* __restrict__ Wrec,   // [U][G4] gate-reordered
    float* hseq,                      // [T][B][U]  (cross-block shared; no restrict)
    unsigned* bar)
{
    extern __shared__ float smem[];
    float* Ws = smem;                 // [512][16]
    float* Hs = smem + 512 * 16;      // [KC][129]

    int tid = threadIdx.x;
    int blk = blockIdx.x;
    int n0 = blk * 16;
    int tx = tid & 3;                 // unit-within-block
    int ty = tid >> 2;                // 0..63, batch pair
    int u  = blk * 4 + tx;

    // Cache W_rec slice in SMEM (once)
    for (int l = tid; l < 512 * 4; l += 256) {      // 2048 float4
        int row = l >> 2, c4 = l & 3;
        *(float4*)&Ws[row * 16 + c4 * 4] =
            *(const float4*)(Wrec + (size_t)row * G4_ + n0 + c4 * 4);
    }

    float creg0 = 0.0f, creg1 = 0.0f;               // cell state in registers
    const float* hp = h0;

    for (int t = 0; t < T_; t++) {
        float acc[2][4];
        #pragma unroll
        for (int i = 0; i < 2; i++)
            #pragma unroll
            for (int j = 0; j < 4; j++) acc[i][j] = 0.0f;

        for (int k0 = 0; k0 < U_; k0 += KC) {
            // stage h chunk transposed: Hs[kk][b], row pitch 129 (conflict-free)
            #pragma unroll
            for (int i = 0; i < 4; i++) {
                int l = tid + i * 256;              // 0..1023 float4
                int b = l >> 3, k4 = l & 7;
                float4 v = __ldcg((const float4*)(hp + (size_t)b * U_ + k0 + k4 * 4));
                Hs[(k4 * 4 + 0) * 129 + b] = v.x;
                Hs[(k4 * 4 + 1) * 129 + b] = v.y;
                Hs[(k4 * 4 + 2) * 129 + b] = v.z;
                Hs[(k4 * 4 + 3) * 129 + b] = v.w;
            }
            __syncthreads();

            #pragma unroll
            for (int kk = 0; kk < KC; kk++) {
                float4 wv = *(float4*)&Ws[(k0 + kk) * 16 + tx * 4];
                float ha = Hs[kk * 129 + ty * 2 + 0];
                float hb = Hs[kk * 129 + ty * 2 + 1];
                acc[0][0] += ha * wv.x; acc[0][1] += ha * wv.y;
                acc[0][2] += ha * wv.z; acc[0][3] += ha * wv.w;
                acc[1][0] += hb * wv.x; acc[1][1] += hb * wv.y;
                acc[1][2] += hb * wv.z; acc[1][3] += hb * wv.w;
            }
            __syncthreads();
        }

        // gates + state update (thread-local), publish h[t]
        #pragma unroll
        for (int i = 0; i < 2; i++) {
            int b = ty * 2 + i;
            const float* xzp = xz + ((size_t)t * B_ + b) * G4_ + n0 + tx * 4;
            float zi = acc[i][0] + xzp[0];
            float zf = acc[i][1] + xzp[1];
            float zg = acc[i][2] + xzp[2];
            float zo = acc[i][3] + xzp[3];
            float ig = 1.0f / (1.0f + expf(-zi));
            float fg = 1.0f / (1.0f + expf(-zf));
            float gg = tanhf(zg);
            float og = 1.0f / (1.0f + expf(-zo));
            float cp = i ? creg1 : creg0;
            float cn = fg * cp + ig * gg;
            if (i) creg1 = cn; else creg0 = cn;
            hseq[((size_t)t * B_ + b) * U_ + u] = og * tanhf(cn);
        }

        // grid barrier: make h[t] globally visible, wait for all blocks
        __threadfence();
        __syncthreads();                 // all threads' stores fenced before arrive
        if (tid == 0) {
            atomicAdd(bar, 1u);
            unsigned target = (unsigned)RBLK * (unsigned)(t + 1);
            while (*(volatile unsigned*)bar < target) {}
        }
        __syncthreads();

        hp = hseq + (size_t)t * B_ * U_;
    }
}

// ---------------------------------------------------------------------------
// In-place row softmax over rows of length CODES_ (1024). One block per row.
// ---------------------------------------------------------------------------
__global__ __launch_bounds__(256) void softmax_kernel(float* __restrict__ out) {
    __shared__ float red[8];
    int tid = threadIdx.x;
    float* p = out + (size_t)blockIdx.x * CODES_;

    float4 v = *(float4*)(p + tid * 4);
    float m = fmaxf(fmaxf(v.x, v.y), fmaxf(v.z, v.w));
    #pragma unroll
    for (int o = 16; o > 0; o >>= 1) m = fmaxf(m, __shfl_xor_sync(0xFFFFFFFFu, m, o));
    if ((tid & 31) == 0) red[tid >> 5] = m;
    __syncthreads();
    float bm = red[0];
    #pragma unroll
    for (int i = 1; i < 8; i++) bm = fmaxf(bm, red[i]);
    __syncthreads();

    v.x = expf(v.x - bm); v.y = expf(v.y - bm);
    v.z = expf(v.z - bm); v.w = expf(v.w - bm);
    float s = v.x + v.y + v.z + v.w;
    #pragma unroll
    for (int o = 16; o > 0; o >>= 1) s += __shfl_xor_sync(0xFFFFFFFFu, s, o);
    if ((tid & 31) == 0) red[tid >> 5] = s;
    __syncthreads();
    float bs = red[0];
    #pragma unroll
    for (int i = 1; i < 8; i++) bs += red[i];
    float inv = 1.0f / bs;
    v.x *= inv; v.y *= inv; v.z *= inv; v.w *= inv;
    *(float4*)(p + tid * 4) = v;
}

// ---------------------------------------------------------------------------
// Launch
// ---------------------------------------------------------------------------
extern "C" void kernel_launch(void* const* d_in, const int* in_sizes, int n_in,
                              void* d_out, int out_size) {
    const float* x       = (const float*)d_in[0];   // [T,B,F]
    const float* mask    = (const float*)d_in[1];   // [T,B]
    const float* W_in    = (const float*)d_in[2];   // [F,4U]
    const float* W_rec   = (const float*)d_in[3];   // [U,4U]
    const float* b_lstm  = (const float*)d_in[4];   // [4U]
    const float* W_dense = (const float*)d_in[5];   // [U,CODES]
    const float* b_dense = (const float*)d_in[6];   // [CODES]
    float* out = (float*)d_out;                     // [T,B,CODES]

    float *xz, *hseq, *h0, *Win4, *Wrec4, *b4;
    unsigned* bar;
    cudaGetSymbolAddress((void**)&xz,    g_xz);
    cudaGetSymbolAddress((void**)&hseq,  g_hseq);
    cudaGetSymbolAddress((void**)&h0,    g_h0);
    cudaGetSymbolAddress((void**)&Win4,  g_Win4);
    cudaGetSymbolAddress((void**)&Wrec4, g_Wrec4);
    cudaGetSymbolAddress((void**)&b4,    g_b4);
    cudaGetSymbolAddress((void**)&bar,   g_bar);

    int lstm_smem = (512 * 16 + KC * 129) * (int)sizeof(float);
    cudaFuncSetAttribute(lstm_persistent,
                         cudaFuncAttributeMaxDynamicSharedMemorySize, lstm_smem);

    // Prep: gate-reorder weights/bias, zero h0, reset barrier
    reorder_gates<<<(F_ * G4_ + 255) / 256, 256>>>(W_in,  Win4,  F_ * G4_);
    reorder_gates<<<(U_ * G4_ + 255) / 256, 256>>>(W_rec, Wrec4, U_ * G4_);
    init_kernel<<<(B_ * U_ + 255) / 256, 256>>>(b_lstm, b4, h0, bar);

    // Phase 1: xz = x @ Win4 + b4   (M=32768, N=2048, K=1024)
    sgemm128<<<dim3(G4_ / 128, ROWS_ / 128), 256>>>(
        x, Win4, b4, nullptr, xz, ROWS_, G4_, F_, 0);

    // Phase 2: full recurrence in ONE persistent kernel
    lstm_persistent<<<RBLK, 256, lstm_smem>>>(h0, xz, Wrec4, hseq, bar);

    // Phase 3: logits = relu((h_seq * mask) @ W_dense + b_dense) -> d_out
    sgemm128<<<dim3(CODES_ / 128, ROWS_ / 128), 256>>>(
        hseq, W_dense, b_dense, mask, out, ROWS_, CODES_, U_, 1);

    // Phase 4: in-place row softmax
    softmax_kernel<<<ROWS_, 256>>>(out);
}

// round 4
// speedup vs baseline: 1.7966x; 1.2221x over previous
#include <cuda_runtime.h>
#include <cuda_bf16.h>
#include <math.h>
#include <stdint.h>

// Problem constants
#define T_   256
#define B_   128
#define F_   1024
#define U_   512
#define G4_  2048   // 4*U
#define CODES_ 1024
#define ROWS_ 32768 // T*B

#define RBLK 128    // persistent recurrence blocks
#define KC   32     // recurrence K chunk

// Tensor GEMM tile
#define BKT  32
#define APITCH 40   // 32 + 8 pad (bf16 elems): 80B rows -> conflict-free ldmatrix
#define BPITCH 136  // 128 + 8 pad: 272B rows -> conflict-free ldmatrix

// ---------------------------------------------------------------------------
// Scratch
// ---------------------------------------------------------------------------
__device__ float g_xz   [(size_t)ROWS_ * G4_];
__device__ float g_hseq [(size_t)ROWS_ * U_];
__device__ float g_h0   [B_ * U_];
__device__ float g_Wrec4[(size_t)U_ * G4_];
__device__ float g_b4   [G4_];
__device__ unsigned g_bar;

// ---------------------------------------------------------------------------
// Weight gate-reorder (W_rec only; W_in used directly with col remap in GEMM? no:
// phase-1 output must be gate-reordered for the recurrence, so we reorder the
// GEMM's B operand instead of the output. Simpler: keep reordering W_in too.)
// ---------------------------------------------------------------------------
__device__ float g_Win4 [(size_t)F_ * G4_];

__global__ void reorder_gates(const float* __restrict__ W, float* __restrict__ W4, int total) {
    int idx = blockIdx.x * blockDim.x + threadIdx.x;
    if (idx >= total) return;
    int col = idx & (G4_ - 1);
    int k   = idx >> 11;
    int u   = col >> 2;
    int g   = col & 3;
    W4[idx] = W[(size_t)k * G4_ + g * U_ + u];
}

__global__ void init_kernel(const float* __restrict__ b_lstm,
                            float* __restrict__ b4,
                            float* __restrict__ h0,
                            unsigned* __restrict__ bar) {
    int idx = blockIdx.x * blockDim.x + threadIdx.x;
    if (idx == 0) *bar = 0u;
    if (idx < G4_) b4[idx] = b_lstm[(idx & 3) * U_ + (idx >> 2)];
    if (idx < B_ * U_) h0[idx] = 0.0f;
}

// ---------------------------------------------------------------------------
// PTX helpers
// ---------------------------------------------------------------------------
__device__ __forceinline__ uint32_t smem_u32(const void* p) {
    return (uint32_t)__cvta_generic_to_shared(p);
}
__device__ __forceinline__ void ldsm_x4(uint32_t& r0, uint32_t& r1, uint32_t& r2, uint32_t& r3, uint32_t a) {
    asm volatile("ldmatrix.sync.aligned.m8n8.x4.shared.b16 {%0,%1,%2,%3},[%4];"
                 : "=r"(r0), "=r"(r1), "=r"(r2), "=r"(r3) : "r"(a));
}
__device__ __forceinline__ void ldsm_x4t(uint32_t& r0, uint32_t& r1, uint32_t& r2, uint32_t& r3, uint32_t a) {
    asm volatile("ldmatrix.sync.aligned.m8n8.x4.trans.shared.b16 {%0,%1,%2,%3},[%4];"
                 : "=r"(r0), "=r"(r1), "=r"(r2), "=r"(r3) : "r"(a));
}
__device__ __forceinline__ void mma_bf16(float c[4], const uint32_t a[4], const uint32_t b[2]) {
    asm volatile(
        "mma.sync.aligned.m16n8k16.row.col.f32.bf16.bf16.f32 "
        "{%0,%1,%2,%3},{%4,%5,%6,%7},{%8,%9},{%0,%1,%2,%3};"
        : "+f"(c[0]), "+f"(c[1]), "+f"(c[2]), "+f"(c[3])
        : "r"(a[0]), "r"(a[1]), "r"(a[2]), "r"(a[3]), "r"(b[0]), "r"(b[1]));
}
__device__ __forceinline__ void split_pair(float x, float y,
                                           __nv_bfloat162* hi, __nv_bfloat162* lo) {
    __nv_bfloat16 hx = __float2bfloat16(x);
    __nv_bfloat16 hy = __float2bfloat16(y);
    __nv_bfloat16 lx = __float2bfloat16(x - __bfloat162float(hx));
    __nv_bfloat16 ly = __float2bfloat16(y - __bfloat162float(hy));
    *hi = __halves2bfloat162(hx, hy);
    *lo = __halves2bfloat162(lx, ly);
}

// ---------------------------------------------------------------------------
// Tensor-core GEMM with on-the-fly bf16 hi/lo split (3xBF16 ~= fp32 accuracy).
// C[M,N] = (A[M,K] * rowscale) @ B[K,N] + bias, optional relu.
// 128x128x32 tiles, 8 warps (4M x 2N), warp tile 32x64, mma.m16n8k16.
// ---------------------------------------------------------------------------
__global__ __launch_bounds__(256) void tgemm128(
    const float* __restrict__ A, const float* __restrict__ Bm,
    const float* __restrict__ bias, const float* __restrict__ mask,
    float* __restrict__ C, int M, int N, int K, int relu)
{
    __shared__ __nv_bfloat16 sAh[128 * APITCH];
    __shared__ __nv_bfloat16 sAl[128 * APITCH];
    __shared__ __nv_bfloat16 sBh[BKT * BPITCH];
    __shared__ __nv_bfloat16 sBl[BKT * BPITCH];

    int tid  = threadIdx.x;
    int warp = tid >> 5, lane = tid & 31;
    int wm = warp >> 1, wn = warp & 1;
    int m0 = blockIdx.y * 128, n0 = blockIdx.x * 128;

    // A loader: row = tid>>1 (0..127), k seg = (tid&1)*16, 16 floats each
    int arow  = tid >> 1;
    int akofs = (tid & 1) * 16;
    const float* Ap = A + (size_t)(m0 + arow) * K + akofs;
    float amul = mask ? mask[m0 + arow] : 1.0f;

    // B loader: k row = tid>>3 (0..31), n seg = (tid&7)*16, 16 floats each
    int brow = tid >> 3;
    int bcol = (tid & 7) * 16;
    const float* Bp = Bm + (size_t)brow * N + n0 + bcol;

    float acc[2][8][4];
    #pragma unroll
    for (int i = 0; i < 2; i++)
        #pragma unroll
        for (int j = 0; j < 8; j++)
            #pragma unroll
            for (int q = 0; q < 4; q++) acc[i][j][q] = 0.0f;

    // ldmatrix base addresses (per-lane, loop-invariant parts)
    int a_r = (lane & 15);          // row within 16
    int a_c = (lane >> 4) * 8;      // 0 or 8
    uint32_t aAh = smem_u32(&sAh[(wm * 32 + a_r) * APITCH + a_c]);
    uint32_t aAl = smem_u32(&sAl[(wm * 32 + a_r) * APITCH + a_c]);
    uint32_t aBh = smem_u32(&sBh[a_r * BPITCH + wn * 64 + a_c]);
    uint32_t aBl = smem_u32(&sBl[a_r * BPITCH + wn * 64 + a_c]);

    float4 apf[4], bpf[4];
    #pragma unroll
    for (int i = 0; i < 4; i++) {
        apf[i] = *(const float4*)(Ap + i * 4);
        bpf[i] = *(const float4*)(Bp + i * 4);
    }

    for (int k0 = 0; k0 < K; k0 += BKT) {
        // convert prefetched fp32 -> bf16 hi/lo in SMEM
        #pragma unroll
        for (int i = 0; i < 4; i++) {
            float ax = apf[i].x * amul, ay = apf[i].y * amul;
            float az = apf[i].z * amul, aw = apf[i].w * amul;
            __nv_bfloat162 h0, l0, h1, l1;
            split_pair(ax, ay, &h0, &l0);
            split_pair(az, aw, &h1, &l1);
            int o = arow * APITCH + akofs + i * 4;
            *(__nv_bfloat162*)&sAh[o]     = h0;
            *(__nv_bfloat162*)&sAh[o + 2] = h1;
            *(__nv_bfloat162*)&sAl[o]     = l0;
            *(__nv_bfloat162*)&sAl[o + 2] = l1;

            split_pair(bpf[i].x, bpf[i].y, &h0, &l0);
            split_pair(bpf[i].z, bpf[i].w, &h1, &l1);
            int ob = brow * BPITCH + bcol + i * 4;
            *(__nv_bfloat162*)&sBh[ob]     = h0;
            *(__nv_bfloat162*)&sBh[ob + 2] = h1;
            *(__nv_bfloat162*)&sBl[ob]     = l0;
            *(__nv_bfloat162*)&sBl[ob + 2] = l1;
        }
        __syncthreads();

        if (k0 + BKT < K) {   // prefetch next chunk during MMA
            #pragma unroll
            for (int i = 0; i < 4; i++) {
                apf[i] = *(const float4*)(Ap + k0 + BKT + i * 4);
                bpf[i] = *(const float4*)(Bp + (size_t)(k0 + BKT) * N + i * 4);
            }
        }

        #pragma unroll
        for (int kk = 0; kk < 2; kk++) {
            uint32_t Ah[2][4], Al[2][4];
            #pragma unroll
            for (int mt = 0; mt < 2; mt++) {
                uint32_t off = (mt * 16) * APITCH * 2 + kk * 16 * 2;  // bytes
                ldsm_x4(Ah[mt][0], Ah[mt][1], Ah[mt][2], Ah[mt][3], aAh + off);
                ldsm_x4(Al[mt][0], Al[mt][1], Al[mt][2], Al[mt][3], aAl + off);
            }
            uint32_t Bh[8][2], Bl[8][2];
            #pragma unroll
            for (int p = 0; p < 4; p++) {
                uint32_t off = (kk * 16) * BPITCH * 2 + p * 16 * 2;   // bytes
                ldsm_x4t(Bh[2*p][0], Bh[2*p][1], Bh[2*p+1][0], Bh[2*p+1][1], aBh + off);
                ldsm_x4t(Bl[2*p][0], Bl[2*p][1], Bl[2*p+1][0], Bl[2*p+1][1], aBl + off);
            }
            #pragma unroll
            for (int mt = 0; mt < 2; mt++)
                #pragma unroll
                for (int nt = 0; nt < 8; nt++) {
                    mma_bf16(acc[mt][nt], Ah[mt], Bh[nt]);
                    mma_bf16(acc[mt][nt], Ah[mt], Bl[nt]);
                    mma_bf16(acc[mt][nt], Al[mt], Bh[nt]);
                }
        }
        __syncthreads();
    }

    // Epilogue: bias (+relu), fp32 store. C fragment: rows lane>>2, +8; cols (lane&3)*2.
    int crow = lane >> 2;
    int ccol = (lane & 3) * 2;
    #pragma unroll
    for (int mt = 0; mt < 2; mt++) {
        int r0 = m0 + wm * 32 + mt * 16 + crow;
        #pragma unroll
        for (int nt = 0; nt < 8; nt++) {
            int cglob = n0 + wn * 64 + nt * 8 + ccol;
            float b0 = bias[cglob], b1 = bias[cglob + 1];
            float2 v0 = { acc[mt][nt][0] + b0, acc[mt][nt][1] + b1 };
            float2 v1 = { acc[mt][nt][2] + b0, acc[mt][nt][3] + b1 };
            if (relu) {
                v0.x = fmaxf(v0.x, 0.f); v0.y = fmaxf(v0.y, 0.f);
                v1.x = fmaxf(v1.x, 0.f); v1.y = fmaxf(v1.y, 0.f);
            }
            *(float2*)(C + (size_t)r0 * N + cglob)       = v0;
            *(float2*)(C + (size_t)(r0 + 8) * N + cglob) = v1;
        }
    }
}

// ---------------------------------------------------------------------------
// Persistent LSTM recurrence (unchanged from R3; known good).
// ---------------------------------------------------------------------------
__global__ __launch_bounds__(256) void lstm_persistent(
    const float* __restrict__ h0,
    const float* __restrict__ xz,
    const float* __restrict__ Wrec,
    float* hseq,
    unsigned* bar)
{
    extern __shared__ float smem[];
    float* Ws = smem;                 // [512][16]
    float* Hs = smem + 512 * 16;      // [KC][129]

    int tid = threadIdx.x;
    int blk = blockIdx.x;
    int n0 = blk * 16;
    int tx = tid & 3;
    int ty = tid >> 2;
    int u  = blk * 4 + tx;

    for (int l = tid; l < 512 * 4; l += 256) {
        int row = l >> 2, c4 = l & 3;
        *(float4*)&Ws[row * 16 + c4 * 4] =
            *(const float4*)(Wrec + (size_t)row * G4_ + n0 + c4 * 4);
    }

    float creg0 = 0.0f, creg1 = 0.0f;
    const float* hp = h0;

    for (int t = 0; t < T_; t++) {
        float acc[2][4];
        #pragma unroll
        for (int i = 0; i < 2; i++)
            #pragma unroll
            for (int j = 0; j < 4; j++) acc[i][j] = 0.0f;

        for (int k0 = 0; k0 < U_; k0 += KC) {
            #pragma unroll
            for (int i = 0; i < 4; i++) {
                int l = tid + i * 256;
                int b = l >> 3, k4 = l & 7;
                float4 v = __ldcg((const float4*)(hp + (size_t)b * U_ + k0 + k4 * 4));
                Hs[(k4 * 4 + 0) * 129 + b] = v.x;
                Hs[(k4 * 4 + 1) * 129 + b] = v.y;
                Hs[(k4 * 4 + 2) * 129 + b] = v.z;
                Hs[(k4 * 4 + 3) * 129 + b] = v.w;
            }
            __syncthreads();

            #pragma unroll
            for (int kk = 0; kk < KC; kk++) {
                float4 wv = *(float4*)&Ws[(k0 + kk) * 16 + tx * 4];
                float ha = Hs[kk * 129 + ty * 2 + 0];
                float hb = Hs[kk * 129 + ty * 2 + 1];
                acc[0][0] += ha * wv.x; acc[0][1] += ha * wv.y;
                acc[0][2] += ha * wv.z; acc[0][3] += ha * wv.w;
                acc[1][0] += hb * wv.x; acc[1][1] += hb * wv.y;
                acc[1][2] += hb * wv.z; acc[1][3] += hb * wv.w;
            }
            __syncthreads();
        }

        #pragma unroll
        for (int i = 0; i < 2; i++) {
            int b = ty * 2 + i;
            const float* xzp = xz + ((size_t)t * B_ + b) * G4_ + n0 + tx * 4;
            float zi = acc[i][0] + xzp[0];
            float zf = acc[i][1] + xzp[1];
            float zg = acc[i][2] + xzp[2];
            float zo = acc[i][3] + xzp[3];
            float ig = 1.0f / (1.0f + expf(-zi));
            float fg = 1.0f / (1.0f + expf(-zf));
            float gg = tanhf(zg);
            float og = 1.0f / (1.0f + expf(-zo));
            float cp = i ? creg1 : creg0;
            float cn = fg * cp + ig * gg;
            if (i) creg1 = cn; else creg0 = cn;
            hseq[((size_t)t * B_ + b) * U_ + u] = og * tanhf(cn);
        }

        __threadfence();
        __syncthreads();
        if (tid == 0) {
            atomicAdd(bar, 1u);
            unsigned target = (unsigned)RBLK * (unsigned)(t + 1);
            while (*(volatile unsigned*)bar < target) {}
        }
        __syncthreads();

        hp = hseq + (size_t)t * B_ * U_;
    }
}

// ---------------------------------------------------------------------------
// In-place row softmax (1024 cols, one block/row).
// ---------------------------------------------------------------------------
__global__ __launch_bounds__(256) void softmax_kernel(float* __restrict__ out) {
    __shared__ float red[8];
    int tid = threadIdx.x;
    float* p = out + (size_t)blockIdx.x * CODES_;

    float4 v = *(float4*)(p + tid * 4);
    float m = fmaxf(fmaxf(v.x, v.y), fmaxf(v.z, v.w));
    #pragma unroll
    for (int o = 16; o > 0; o >>= 1) m = fmaxf(m, __shfl_xor_sync(0xFFFFFFFFu, m, o));
    if ((tid & 31) == 0) red[tid >> 5] = m;
    __syncthreads();
    float bm = red[0];
    #pragma unroll
    for (int i = 1; i < 8; i++) bm = fmaxf(bm, red[i]);
    __syncthreads();

    v.x = expf(v.x - bm); v.y = expf(v.y - bm);
    v.z = expf(v.z - bm); v.w = expf(v.w - bm);
    float s = v.x + v.y + v.z + v.w;
    #pragma unroll
    for (int o = 16; o > 0; o >>= 1) s += __shfl_xor_sync(0xFFFFFFFFu, s, o);
    if ((tid & 31) == 0) red[tid >> 5] = s;
    __syncthreads();
    float bs = red[0];
    #pragma unroll
    for (int i = 1; i < 8; i++) bs += red[i];
    float inv = 1.0f / bs;
    v.x *= inv; v.y *= inv; v.z *= inv; v.w *= inv;
    *(float4*)(p + tid * 4) = v;
}

// ---------------------------------------------------------------------------
// Launch
// ---------------------------------------------------------------------------
extern "C" void kernel_launch(void* const* d_in, const int* in_sizes, int n_in,
                              void* d_out, int out_size) {
    const float* x       = (const float*)d_in[0];
    const float* mask    = (const float*)d_in[1];
    const float* W_in    = (const float*)d_in[2];
    const float* W_rec   = (const float*)d_in[3];
    const float* b_lstm  = (const float*)d_in[4];
    const float* W_dense = (const float*)d_in[5];
    const float* b_dense = (const float*)d_in[6];
    float* out = (float*)d_out;

    float *xz, *hseq, *h0, *Win4, *Wrec4, *b4;
    unsigned* bar;
    cudaGetSymbolAddress((void**)&xz,    g_xz);
    cudaGetSymbolAddress((void**)&hseq,  g_hseq);
    cudaGetSymbolAddress((void**)&h0,    g_h0);
    cudaGetSymbolAddress((void**)&Win4,  g_Win4);
    cudaGetSymbolAddress((void**)&Wrec4, g_Wrec4);
    cudaGetSymbolAddress((void**)&b4,    g_b4);
    cudaGetSymbolAddress((void**)&bar,   g_bar);

    int lstm_smem = (512 * 16 + KC * 129) * (int)sizeof(float);
    cudaFuncSetAttribute(lstm_persistent,
                         cudaFuncAttributeMaxDynamicSharedMemorySize, lstm_smem);

    reorder_gates<<<(F_ * G4_ + 255) / 256, 256>>>(W_in,  Win4,  F_ * G4_);
    reorder_gates<<<(U_ * G4_ + 255) / 256, 256>>>(W_rec, Wrec4, U_ * G4_);
    init_kernel<<<(B_ * U_ + 255) / 256, 256>>>(b_lstm, b4, h0, bar);

    // Phase 1: xz = x @ Win4 + b4 (tensor cores, 3xBF16)
    tgemm128<<<dim3(G4_ / 128, ROWS_ / 128), 256>>>(
        x, Win4, b4, nullptr, xz, ROWS_, G4_, F_, 0);

    // Phase 2: persistent recurrence
    lstm_persistent<<<RBLK, 256, lstm_smem>>>(h0, xz, Wrec4, hseq, bar);

    // Phase 3: logits = relu((h_seq*mask) @ W_dense + b_dense) (tensor cores)
    tgemm128<<<dim3(CODES_ / 128, ROWS_ / 128), 256>>>(
        hseq, W_dense, b_dense, mask, out, ROWS_, CODES_, U_, 1);

    // Phase 4: softmax
    softmax_kernel<<<ROWS_, 256>>>(out);
}

// round 5
// speedup vs baseline: 1.8610x; 1.0358x over previous
#include <cuda_runtime.h>
#include <cuda_bf16.h>
#include <math.h>
#include <stdint.h>

// Problem constants
#define T_   256
#define B_   128
#define F_   1024
#define U_   512
#define G4_  2048   // 4*U
#define CODES_ 1024
#define ROWS_ 32768 // T*B

#define RBLK 128    // persistent recurrence blocks
#define KC   32     // recurrence K chunk

// Tensor GEMM tile
#define BKT  32
#define APITCH 40   // 32 + 8 pad (bf16): 80B rows, 16B-multiple, conflict-free ldmatrix
#define BPITCH 136  // 128 + 8 pad: 272B rows, 16B-multiple

#define SA_ELEM (128 * APITCH)   // 5120 bf16 per A matrix per stage
#define SB_ELEM (BKT * BPITCH)   // 4352 bf16 per B matrix per stage
#define STAGE_ELEM (2 * SA_ELEM + 2 * SB_ELEM)  // 18944
#define GEMM_SMEM (2 * STAGE_ELEM * 2)          // bytes: 75776

// ---------------------------------------------------------------------------
// Scratch
// ---------------------------------------------------------------------------
__device__ float g_xz   [(size_t)ROWS_ * G4_];
__device__ float g_hseq [(size_t)ROWS_ * U_];
__device__ float g_h0   [B_ * U_];
__device__ float g_Wrec4[(size_t)U_ * G4_];
__device__ float g_b4   [G4_];
__device__ unsigned g_bar;

// bf16 hi/lo pre-split operands
__device__ __nv_bfloat16 g_xh [(size_t)ROWS_ * F_];
__device__ __nv_bfloat16 g_xl [(size_t)ROWS_ * F_];
__device__ __nv_bfloat16 g_Wih[(size_t)F_ * G4_];
__device__ __nv_bfloat16 g_Wil[(size_t)F_ * G4_];
__device__ __nv_bfloat16 g_Wdh[(size_t)U_ * CODES_];
__device__ __nv_bfloat16 g_Wdl[(size_t)U_ * CODES_];
__device__ __nv_bfloat16 g_hh [(size_t)ROWS_ * U_];
__device__ __nv_bfloat16 g_hl [(size_t)ROWS_ * U_];

// ---------------------------------------------------------------------------
// Helpers
// ---------------------------------------------------------------------------
__device__ __forceinline__ uint32_t smem_u32(const void* p) {
    return (uint32_t)__cvta_generic_to_shared(p);
}
__device__ __forceinline__ void cpa16(uint32_t dst, const void* src) {
    asm volatile("cp.async.cg.shared.global [%0], [%1], 16;\n" :: "r"(dst), "l"(src));
}
__device__ __forceinline__ void cpa_commit() {
    asm volatile("cp.async.commit_group;\n" ::);
}
__device__ __forceinline__ void cpa_wait0() {
    asm volatile("cp.async.wait_group 0;\n" ::);
}
__device__ __forceinline__ void ldsm_x4(uint32_t& r0, uint32_t& r1, uint32_t& r2, uint32_t& r3, uint32_t a) {
    asm volatile("ldmatrix.sync.aligned.m8n8.x4.shared.b16 {%0,%1,%2,%3},[%4];"
                 : "=r"(r0), "=r"(r1), "=r"(r2), "=r"(r3) : "r"(a));
}
__device__ __forceinline__ void ldsm_x4t(uint32_t& r0, uint32_t& r1, uint32_t& r2, uint32_t& r3, uint32_t a) {
    asm volatile("ldmatrix.sync.aligned.m8n8.x4.trans.shared.b16 {%0,%1,%2,%3},[%4];"
                 : "=r"(r0), "=r"(r1), "=r"(r2), "=r"(r3) : "r"(a));
}
__device__ __forceinline__ void mma_bf16(float c[4], const uint32_t a[4], const uint32_t b[2]) {
    asm volatile(
        "mma.sync.aligned.m16n8k16.row.col.f32.bf16.bf16.f32 "
        "{%0,%1,%2,%3},{%4,%5,%6,%7},{%8,%9},{%0,%1,%2,%3};"
        : "+f"(c[0]), "+f"(c[1]), "+f"(c[2]), "+f"(c[3])
        : "r"(a[0]), "r"(a[1]), "r"(a[2]), "r"(a[3]), "r"(b[0]), "r"(b[1]));
}

// ---------------------------------------------------------------------------
// Pre-pass kernels: gate reorder + bf16 hi/lo splits
// ---------------------------------------------------------------------------
__global__ void reorder_gates(const float* __restrict__ W, float* __restrict__ W4, int total) {
    int idx = blockIdx.x * blockDim.x + threadIdx.x;
    if (idx >= total) return;
    int col = idx & (G4_ - 1);
    int k   = idx >> 11;
    int u   = col >> 2;
    int g   = col & 3;
    W4[idx] = W[(size_t)k * G4_ + g * U_ + u];
}

// gate-reorder + split (for W_in)
__global__ void reorder_split(const float* __restrict__ W,
                              __nv_bfloat16* __restrict__ hi,
                              __nv_bfloat16* __restrict__ lo, int total) {
    int idx = blockIdx.x * blockDim.x + threadIdx.x;
    if (idx >= total) return;
    int col = idx & (G4_ - 1);
    int k   = idx >> 11;
    float v = W[(size_t)k * G4_ + (col & 3) * U_ + (col >> 2)];
    __nv_bfloat16 h = __float2bfloat16(v);
    hi[idx] = h;
    lo[idx] = __float2bfloat16(v - __bfloat162float(h));
}

// plain split, float4-vectorized (n must be /4)
__global__ void convert_split(const float* __restrict__ src,
                              __nv_bfloat16* __restrict__ hi,
                              __nv_bfloat16* __restrict__ lo, int n4) {
    int idx = blockIdx.x * blockDim.x + threadIdx.x;
    if (idx >= n4) return;
    float4 v = *(const float4*)(src + (size_t)idx * 4);
    __nv_bfloat16 h0 = __float2bfloat16(v.x), h1 = __float2bfloat16(v.y);
    __nv_bfloat16 h2 = __float2bfloat16(v.z), h3 = __float2bfloat16(v.w);
    __nv_bfloat162 ph0 = __halves2bfloat162(h0, h1), ph1 = __halves2bfloat162(h2, h3);
    __nv_bfloat162 pl0 = __halves2bfloat162(__float2bfloat16(v.x - __bfloat162float(h0)),
                                            __float2bfloat16(v.y - __bfloat162float(h1)));
    __nv_bfloat162 pl1 = __halves2bfloat162(__float2bfloat16(v.z - __bfloat162float(h2)),
                                            __float2bfloat16(v.w - __bfloat162float(h3)));
    *(__nv_bfloat162*)(hi + (size_t)idx * 4)     = ph0;
    *(__nv_bfloat162*)(hi + (size_t)idx * 4 + 2) = ph1;
    *(__nv_bfloat162*)(lo + (size_t)idx * 4)     = pl0;
    *(__nv_bfloat162*)(lo + (size_t)idx * 4 + 2) = pl1;
}

// masked split for h_seq (rows of length U_)
__global__ void convert_mask(const float* __restrict__ hseq,
                             const float* __restrict__ mask,
                             __nv_bfloat16* __restrict__ hi,
                             __nv_bfloat16* __restrict__ lo, int n4) {
    int idx = blockIdx.x * blockDim.x + threadIdx.x;
    if (idx >= n4) return;
    float m = mask[(idx * 4) >> 9];   // U_ = 512
    float4 v = *(const float4*)(hseq + (size_t)idx * 4);
    v.x *= m; v.y *= m; v.z *= m; v.w *= m;
    __nv_bfloat16 h0 = __float2bfloat16(v.x), h1 = __float2bfloat16(v.y);
    __nv_bfloat16 h2 = __float2bfloat16(v.z), h3 = __float2bfloat16(v.w);
    *(__nv_bfloat162*)(hi + (size_t)idx * 4)     = __halves2bfloat162(h0, h1);
    *(__nv_bfloat162*)(hi + (size_t)idx * 4 + 2) = __halves2bfloat162(h2, h3);
    *(__nv_bfloat162*)(lo + (size_t)idx * 4)     =
        __halves2bfloat162(__float2bfloat16(v.x - __bfloat162float(h0)),
                           __float2bfloat16(v.y - __bfloat162float(h1)));
    *(__nv_bfloat162*)(lo + (size_t)idx * 4 + 2) =
        __halves2bfloat162(__float2bfloat16(v.z - __bfloat162float(h2)),
                           __float2bfloat16(v.w - __bfloat162float(h3)));
}

__global__ void init_kernel(const float* __restrict__ b_lstm,
                            float* __restrict__ b4,
                            float* __restrict__ h0,
                            unsigned* __restrict__ bar) {
    int idx = blockIdx.x * blockDim.x + threadIdx.x;
    if (idx == 0) *bar = 0u;
    if (idx < G4_) b4[idx] = b_lstm[(idx & 3) * U_ + (idx >> 2)];
    if (idx < B_ * U_) h0[idx] = 0.0f;
}

// ---------------------------------------------------------------------------
// Tensor-core GEMM on pre-split bf16 hi/lo operands (3-term 3xBF16).
// C[M,N] = A @ B + bias, optional relu. 128x128x32 tiles, 8 warps (4x2),
// cp.async double-buffered SMEM, ldmatrix, mma.m16n8k16.
// ---------------------------------------------------------------------------
__global__ __launch_bounds__(256) void tgemm2(
    const __nv_bfloat16* __restrict__ Ah, const __nv_bfloat16* __restrict__ Al,
    const __nv_bfloat16* __restrict__ Bh, const __nv_bfloat16* __restrict__ Bl,
    const float* __restrict__ bias, float* __restrict__ C,
    int M, int N, int K, int relu)
{
    extern __shared__ __nv_bfloat16 ts[];

    int tid  = threadIdx.x;
    int warp = tid >> 5, lane = tid & 31;
    int wm = warp >> 1, wn = warp & 1;
    int m0 = blockIdx.y * 128, n0 = blockIdx.x * 128;

    // loader indices
    int arow = tid >> 1;            // A: 2 chunks/thread/matrix: (tid, tid+256)
    int aseg0 = (tid & 1) * 2;      // chunk c: row=c>>2, seg=c&3 -> thread covers segs {2b,2b+1}? 
    // simpler: chunk ids c1=tid, c2=tid+256
    int a1r = tid >> 2,        a1s = tid & 3;
    int a2r = (tid + 256) >> 2, a2s = (tid + 256) & 3;
    int b1r = tid >> 4,        b1s = tid & 15;
    int b2r = (tid + 256) >> 4, b2s = (tid + 256) & 15;
    (void)arow; (void)aseg0;

    float acc[2][8][4];
    #pragma unroll
    for (int i = 0; i < 2; i++)
        #pragma unroll
        for (int j = 0; j < 8; j++)
            #pragma unroll
            for (int q = 0; q < 4; q++) acc[i][j][q] = 0.0f;

    // per-lane ldmatrix offsets (element units within each matrix tile)
    int a_r = (lane & 15);
    int a_c = (lane >> 4) * 8;
    int aoffA = (wm * 32 + a_r) * APITCH + a_c;
    int aoffB = a_r * BPITCH + wn * 64 + a_c;

    int KT = K / BKT;

    // stage loader
    auto load_stage = [&](int kt, int s) {
        __nv_bfloat16* st = ts + s * STAGE_ELEM;
        __nv_bfloat16* sAh = st;
        __nv_bfloat16* sAl = st + SA_ELEM;
        __nv_bfloat16* sBh = st + 2 * SA_ELEM;
        __nv_bfloat16* sBl = st + 2 * SA_ELEM + SB_ELEM;
        int k0 = kt * BKT;
        const __nv_bfloat16* gAh = Ah + (size_t)m0 * K + k0;
        const __nv_bfloat16* gAl = Al + (size_t)m0 * K + k0;
        const __nv_bfloat16* gBh = Bh + (size_t)k0 * N + n0;
        const __nv_bfloat16* gBl = Bl + (size_t)k0 * N + n0;
        cpa16(smem_u32(sAh + a1r * APITCH + a1s * 8), gAh + (size_t)a1r * K + a1s * 8);
        cpa16(smem_u32(sAh + a2r * APITCH + a2s * 8), gAh + (size_t)a2r * K + a2s * 8);
        cpa16(smem_u32(sAl + a1r * APITCH + a1s * 8), gAl + (size_t)a1r * K + a1s * 8);
        cpa16(smem_u32(sAl + a2r * APITCH + a2s * 8), gAl + (size_t)a2r * K + a2s * 8);
        cpa16(smem_u32(sBh + b1r * BPITCH + b1s * 8), gBh + (size_t)b1r * N + b1s * 8);
        cpa16(smem_u32(sBh + b2r * BPITCH + b2s * 8), gBh + (size_t)b2r * N + b2s * 8);
        cpa16(smem_u32(sBl + b1r * BPITCH + b1s * 8), gBl + (size_t)b1r * N + b1s * 8);
        cpa16(smem_u32(sBl + b2r * BPITCH + b2s * 8), gBl + (size_t)b2r * N + b2s * 8);
    };

    load_stage(0, 0);
    cpa_commit();
    cpa_wait0();
    __syncthreads();

    for (int kt = 0; kt < KT; kt++) {
        int cur = kt & 1;
        if (kt + 1 < KT) {
            load_stage(kt + 1, cur ^ 1);
            cpa_commit();
        }

        __nv_bfloat16* st = ts + cur * STAGE_ELEM;
        uint32_t aAh = smem_u32(st + aoffA);
        uint32_t aAl = smem_u32(st + SA_ELEM + aoffA);
        uint32_t aBh = smem_u32(st + 2 * SA_ELEM + aoffB);
        uint32_t aBl = smem_u32(st + 2 * SA_ELEM + SB_ELEM + aoffB);

        #pragma unroll
        for (int kk = 0; kk < 2; kk++) {
            uint32_t Ahf[2][4], Alf[2][4];
            #pragma unroll
            for (int mt = 0; mt < 2; mt++) {
                uint32_t off = (mt * 16) * APITCH * 2 + kk * 16 * 2;   // bytes
                ldsm_x4(Ahf[mt][0], Ahf[mt][1], Ahf[mt][2], Ahf[mt][3], aAh + off);
                ldsm_x4(Alf[mt][0], Alf[mt][1], Alf[mt][2], Alf[mt][3], aAl + off);
            }
            uint32_t Bhf[8][2], Blf[8][2];
            #pragma unroll
            for (int p = 0; p < 4; p++) {
                uint32_t off = (kk * 16) * BPITCH * 2 + p * 16 * 2;    // bytes
                ldsm_x4t(Bhf[2*p][0], Bhf[2*p][1], Bhf[2*p+1][0], Bhf[2*p+1][1], aBh + off);
                ldsm_x4t(Blf[2*p][0], Blf[2*p][1], Blf[2*p+1][0], Blf[2*p+1][1], aBl + off);
            }
            #pragma unroll
            for (int mt = 0; mt < 2; mt++)
                #pragma unroll
                for (int nt = 0; nt < 8; nt++) {
                    mma_bf16(acc[mt][nt], Ahf[mt], Bhf[nt]);
                    mma_bf16(acc[mt][nt], Ahf[mt], Blf[nt]);
                    mma_bf16(acc[mt][nt], Alf[mt], Bhf[nt]);
                }
        }

        if (kt + 1 < KT) cpa_wait0();
        __syncthreads();
    }

    // Epilogue
    int crow = lane >> 2;
    int ccol = (lane & 3) * 2;
    #pragma unroll
    for (int mt = 0; mt < 2; mt++) {
        int r0 = m0 + wm * 32 + mt * 16 + crow;
        #pragma unroll
        for (int nt = 0; nt < 8; nt++) {
            int cglob = n0 + wn * 64 + nt * 8 + ccol;
            float b0 = bias[cglob], b1 = bias[cglob + 1];
            float2 v0 = { acc[mt][nt][0] + b0, acc[mt][nt][1] + b1 };
            float2 v1 = { acc[mt][nt][2] + b0, acc[mt][nt][3] + b1 };
            if (relu) {
                v0.x = fmaxf(v0.x, 0.f); v0.y = fmaxf(v0.y, 0.f);
                v1.x = fmaxf(v1.x, 0.f); v1.y = fmaxf(v1.y, 0.f);
            }
            *(float2*)(C + (size_t)r0 * N + cglob)       = v0;
            *(float2*)(C + (size_t)(r0 + 8) * N + cglob) = v1;
        }
    }
}

// ---------------------------------------------------------------------------
// Persistent LSTM recurrence (unchanged; known good).
// ---------------------------------------------------------------------------
__global__ __launch_bounds__(256) void lstm_persistent(
    const float* __restrict__ h0,
    const float* __restrict__ xz,
    const float* __restrict__ Wrec,
    float* hseq,
    unsigned* bar)
{
    extern __shared__ float smemf[];
    float* Ws = smemf;                // [512][16]
    float* Hs = smemf + 512 * 16;     // [KC][129]

    int tid = threadIdx.x;
    int blk = blockIdx.x;
    int n0 = blk * 16;
    int tx = tid & 3;
    int ty = tid >> 2;
    int u  = blk * 4 + tx;

    for (int l = tid; l < 512 * 4; l += 256) {
        int row = l >> 2, c4 = l & 3;
        *(float4*)&Ws[row * 16 + c4 * 4] =
            *(const float4*)(Wrec + (size_t)row * G4_ + n0 + c4 * 4);
    }

    float creg0 = 0.0f, creg1 = 0.0f;
    const float* hp = h0;

    for (int t = 0; t < T_; t++) {
        float acc[2][4];
        #pragma unroll
        for (int i = 0; i < 2; i++)
            #pragma unroll
            for (int j = 0; j < 4; j++) acc[i][j] = 0.0f;

        for (int k0 = 0; k0 < U_; k0 += KC) {
            #pragma unroll
            for (int i = 0; i < 4; i++) {
                int l = tid + i * 256;
                int b = l >> 3, k4 = l & 7;
                float4 v = __ldcg((const float4*)(hp + (size_t)b * U_ + k0 + k4 * 4));
                Hs[(k4 * 4 + 0) * 129 + b] = v.x;
                Hs[(k4 * 4 + 1) * 129 + b] = v.y;
                Hs[(k4 * 4 + 2) * 129 + b] = v.z;
                Hs[(k4 * 4 + 3) * 129 + b] = v.w;
            }
            __syncthreads();

            #pragma unroll
            for (int kk = 0; kk < KC; kk++) {
                float4 wv = *(float4*)&Ws[(k0 + kk) * 16 + tx * 4];
                float ha = Hs[kk * 129 + ty * 2 + 0];
                float hb = Hs[kk * 129 + ty * 2 + 1];
                acc[0][0] += ha * wv.x; acc[0][1] += ha * wv.y;
                acc[0][2] += ha * wv.z; acc[0][3] += ha * wv.w;
                acc[1][0] += hb * wv.x; acc[1][1] += hb * wv.y;
                acc[1][2] += hb * wv.z; acc[1][3] += hb * wv.w;
            }
            __syncthreads();
        }

        #pragma unroll
        for (int i = 0; i < 2; i++) {
            int b = ty * 2 + i;
            const float* xzp = xz + ((size_t)t * B_ + b) * G4_ + n0 + tx * 4;
            float zi = acc[i][0] + xzp[0];
            float zf = acc[i][1] + xzp[1];
            float zg = acc[i][2] + xzp[2];
            float zo = acc[i][3] + xzp[3];
            float ig = 1.0f / (1.0f + expf(-zi));
            float fg = 1.0f / (1.0f + expf(-zf));
            float gg = tanhf(zg);
            float og = 1.0f / (1.0f + expf(-zo));
            float cp = i ? creg1 : creg0;
            float cn = fg * cp + ig * gg;
            if (i) creg1 = cn; else creg0 = cn;
            hseq[((size_t)t * B_ + b) * U_ + u] = og * tanhf(cn);
        }

        __threadfence();
        __syncthreads();
        if (tid == 0) {
            atomicAdd(bar, 1u);
            unsigned target = (unsigned)RBLK * (unsigned)(t + 1);
            while (*(volatile unsigned*)bar < target) {}
        }
        __syncthreads();

        hp = hseq + (size_t)t * B_ * U_;
    }
}

// ---------------------------------------------------------------------------
// In-place row softmax (1024 cols, one block/row).
// ---------------------------------------------------------------------------
__global__ __launch_bounds__(256) void softmax_kernel(float* __restrict__ out) {
    __shared__ float red[8];
    int tid = threadIdx.x;
    float* p = out + (size_t)blockIdx.x * CODES_;

    float4 v = *(float4*)(p + tid * 4);
    float m = fmaxf(fmaxf(v.x, v.y), fmaxf(v.z, v.w));
    #pragma unroll
    for (int o = 16; o > 0; o >>= 1) m = fmaxf(m, __shfl_xor_sync(0xFFFFFFFFu, m, o));
    if ((tid & 31) == 0) red[tid >> 5] = m;
    __syncthreads();
    float bm = red[0];
    #pragma unroll
    for (int i = 1; i < 8; i++) bm = fmaxf(bm, red[i]);
    __syncthreads();

    v.x = expf(v.x - bm); v.y = expf(v.y - bm);
    v.z = expf(v.z - bm); v.w = expf(v.w - bm);
    float s = v.x + v.y + v.z + v.w;
    #pragma unroll
    for (int o = 16; o > 0; o >>= 1) s += __shfl_xor_sync(0xFFFFFFFFu, s, o);
    if ((tid & 31) == 0) red[tid >> 5] = s;
    __syncthreads();
    float bs = red[0];
    #pragma unroll
    for (int i = 1; i < 8; i++) bs += red[i];
    float inv = 1.0f / bs;
    v.x *= inv; v.y *= inv; v.z *= inv; v.w *= inv;
    *(float4*)(p + tid * 4) = v;
}

// ---------------------------------------------------------------------------
// Launch
// ---------------------------------------------------------------------------
extern "C" void kernel_launch(void* const* d_in, const int* in_sizes, int n_in,
                              void* d_out, int out_size) {
    const float* x       = (const float*)d_in[0];
    const float* mask    = (const float*)d_in[1];
    const float* W_in    = (const float*)d_in[2];
    const float* W_rec   = (const float*)d_in[3];
    const float* b_lstm  = (const float*)d_in[4];
    const float* W_dense = (const float*)d_in[5];
    const float* b_dense = (const float*)d_in[6];
    float* out = (float*)d_out;

    float *xz, *hseq, *h0, *Wrec4, *b4;
    unsigned* bar;
    __nv_bfloat16 *xh, *xl, *Wih, *Wil, *Wdh, *Wdl, *hh, *hl;
    cudaGetSymbolAddress((void**)&xz,    g_xz);
    cudaGetSymbolAddress((void**)&hseq,  g_hseq);
    cudaGetSymbolAddress((void**)&h0,    g_h0);
    cudaGetSymbolAddress((void**)&Wrec4, g_Wrec4);
    cudaGetSymbolAddress((void**)&b4,    g_b4);
    cudaGetSymbolAddress((void**)&bar,   g_bar);
    cudaGetSymbolAddress((void**)&xh,    g_xh);
    cudaGetSymbolAddress((void**)&xl,    g_xl);
    cudaGetSymbolAddress((void**)&Wih,   g_Wih);
    cudaGetSymbolAddress((void**)&Wil,   g_Wil);
    cudaGetSymbolAddress((void**)&Wdh,   g_Wdh);
    cudaGetSymbolAddress((void**)&Wdl,   g_Wdl);
    cudaGetSymbolAddress((void**)&hh,    g_hh);
    cudaGetSymbolAddress((void**)&hl,    g_hl);

    int lstm_smem = (512 * 16 + KC * 129) * (int)sizeof(float);
    cudaFuncSetAttribute(lstm_persistent,
                         cudaFuncAttributeMaxDynamicSharedMemorySize, lstm_smem);
    cudaFuncSetAttribute(tgemm2,
                         cudaFuncAttributeMaxDynamicSharedMemorySize, GEMM_SMEM);

    // Pre-passes
    reorder_gates<<<(U_ * G4_ + 255) / 256, 256>>>(W_rec, Wrec4, U_ * G4_);
    reorder_split<<<(F_ * G4_ + 255) / 256, 256>>>(W_in, Wih, Wil, F_ * G4_);
    convert_split<<<(U_ * CODES_ / 4 + 255) / 256, 256>>>(W_dense, Wdh, Wdl, U_ * CODES_ / 4);
    convert_split<<<((int)((size_t)ROWS_ * F_ / 4) + 255) / 256, 256>>>(x, xh, xl, (int)((size_t)ROWS_ * F_ / 4));
    init_kernel<<<(B_ * U_ + 255) / 256, 256>>>(b_lstm, b4, h0, bar);

    // Phase 1: xz = x @ Win4 + b4 (tensor, pre-split operands)
    tgemm2<<<dim3(G4_ / 128, ROWS_ / 128), 256, GEMM_SMEM>>>(
        xh, xl, Wih, Wil, b4, xz, ROWS_, G4_, F_, 0);

    // Phase 2: persistent recurrence
    lstm_persistent<<<RBLK, 256, lstm_smem>>>(h0, xz, Wrec4, hseq, bar);

    // Phase 2.5: masked h -> bf16 hi/lo
    convert_mask<<<((int)((size_t)ROWS_ * U_ / 4) + 255) / 256, 256>>>(
        hseq, mask, hh, hl, (int)((size_t)ROWS_ * U_ / 4));

    // Phase 3: logits = relu(masked_h @ W_dense + b_dense)
    tgemm2<<<dim3(CODES_ / 128, ROWS_ / 128), 256, GEMM_SMEM>>>(
        hh, hl, Wdh, Wdl, b_dense, out, ROWS_, CODES_, U_, 1);

    // Phase 4: softmax
    softmax_kernel<<<ROWS_, 256>>>(out);
}

// round 7
// speedup vs baseline: 1.9196x; 1.0315x over previous
#include <cuda_runtime.h>
#include <cuda_bf16.h>
#include <math.h>
#include <stdint.h>

// Problem constants
#define T_   256
#define B_   128
#define F_   1024
#define U_   512
#define G4_  2048   // 4*U
#define CODES_ 1024
#define ROWS_ 32768 // T*B

#define RBLK 128    // persistent recurrence blocks
#define KC   32     // recurrence K chunk

// Tensor GEMM tile
#define BKT  32
#define APITCH 40   // 32 + 8 pad (bf16): 80B rows, 16B-multiple, conflict-free ldmatrix
#define BPITCH 136  // 128 + 8 pad: 272B rows, 16B-multiple

#define SA_ELEM (128 * APITCH)   // 5120 bf16 per A matrix per stage
#define SB_ELEM (BKT * BPITCH)   // 4352 bf16 per B matrix per stage
#define STAGE_ELEM (2 * SA_ELEM + 2 * SB_ELEM)  // 18944
#define GEMM_SMEM (2 * STAGE_ELEM * 2)          // bytes: 75776

// ---------------------------------------------------------------------------
// Scratch
// ---------------------------------------------------------------------------
__device__ float g_xz   [(size_t)ROWS_ * G4_];
__device__ float g_hseq [(size_t)ROWS_ * U_];
__device__ float g_h0   [B_ * U_];
__device__ float g_Wrec4[(size_t)U_ * G4_];
__device__ float g_b4   [G4_];
__device__ unsigned g_bar;

// bf16 hi/lo pre-split operands
__device__ __nv_bfloat16 g_xh [(size_t)ROWS_ * F_];
__device__ __nv_bfloat16 g_xl [(size_t)ROWS_ * F_];
__device__ __nv_bfloat16 g_Wih[(size_t)F_ * G4_];
__device__ __nv_bfloat16 g_Wil[(size_t)F_ * G4_];
__device__ __nv_bfloat16 g_Wdh[(size_t)U_ * CODES_];
__device__ __nv_bfloat16 g_Wdl[(size_t)U_ * CODES_];
__device__ __nv_bfloat16 g_hh [(size_t)ROWS_ * U_];
__device__ __nv_bfloat16 g_hl [(size_t)ROWS_ * U_];

// ---------------------------------------------------------------------------
// Helpers
// ---------------------------------------------------------------------------
__device__ __forceinline__ uint32_t smem_u32(const void* p) {
    return (uint32_t)__cvta_generic_to_shared(p);
}
__device__ __forceinline__ void cpa16(uint32_t dst, const void* src) {
    asm volatile("cp.async.cg.shared.global [%0], [%1], 16;\n" :: "r"(dst), "l"(src));
}
__device__ __forceinline__ void cpa_commit() {
    asm volatile("cp.async.commit_group;\n" ::);
}
__device__ __forceinline__ void cpa_wait0() {
    asm volatile("cp.async.wait_group 0;\n" ::);
}
__device__ __forceinline__ void ldsm_x4(uint32_t& r0, uint32_t& r1, uint32_t& r2, uint32_t& r3, uint32_t a) {
    asm volatile("ldmatrix.sync.aligned.m8n8.x4.shared.b16 {%0,%1,%2,%3},[%4];"
                 : "=r"(r0), "=r"(r1), "=r"(r2), "=r"(r3) : "r"(a));
}
__device__ __forceinline__ void ldsm_x4t(uint32_t& r0, uint32_t& r1, uint32_t& r2, uint32_t& r3, uint32_t a) {
    asm volatile("ldmatrix.sync.aligned.m8n8.x4.trans.shared.b16 {%0,%1,%2,%3},[%4];"
                 : "=r"(r0), "=r"(r1), "=r"(r2), "=r"(r3) : "r"(a));
}
__device__ __forceinline__ void mma_bf16(float c[4], const uint32_t a[4], const uint32_t b[2]) {
    asm volatile(
        "mma.sync.aligned.m16n8k16.row.col.f32.bf16.bf16.f32 "
        "{%0,%1,%2,%3},{%4,%5,%6,%7},{%8,%9},{%0,%1,%2,%3};"
        : "+f"(c[0]), "+f"(c[1]), "+f"(c[2]), "+f"(c[3])
        : "r"(a[0]), "r"(a[1]), "r"(a[2]), "r"(a[3]), "r"(b[0]), "r"(b[1]));
}

// ---------------------------------------------------------------------------
// Pre-pass kernels: gate reorder + bf16 hi/lo splits
// ---------------------------------------------------------------------------
__global__ void reorder_gates(const float* __restrict__ W, float* __restrict__ W4, int total) {
    int idx = blockIdx.x * blockDim.x + threadIdx.x;
    if (idx >= total) return;
    int col = idx & (G4_ - 1);
    int k   = idx >> 11;
    int u   = col >> 2;
    int g   = col & 3;
    W4[idx] = W[(size_t)k * G4_ + g * U_ + u];
}

// gate-reorder + split (for W_in)
__global__ void reorder_split(const float* __restrict__ W,
                              __nv_bfloat16* __restrict__ hi,
                              __nv_bfloat16* __restrict__ lo, int total) {
    int idx = blockIdx.x * blockDim.x + threadIdx.x;
    if (idx >= total) return;
    int col = idx & (G4_ - 1);
    int k   = idx >> 11;
    float v = W[(size_t)k * G4_ + (col & 3) * U_ + (col >> 2)];
    __nv_bfloat16 h = __float2bfloat16(v);
    hi[idx] = h;
    lo[idx] = __float2bfloat16(v - __bfloat162float(h));
}

// plain split, float4-vectorized (n must be /4)
__global__ void convert_split(const float* __restrict__ src,
                              __nv_bfloat16* __restrict__ hi,
                              __nv_bfloat16* __restrict__ lo, int n4) {
    int idx = blockIdx.x * blockDim.x + threadIdx.x;
    if (idx >= n4) return;
    float4 v = *(const float4*)(src + (size_t)idx * 4);
    __nv_bfloat16 h0 = __float2bfloat16(v.x), h1 = __float2bfloat16(v.y);
    __nv_bfloat16 h2 = __float2bfloat16(v.z), h3 = __float2bfloat16(v.w);
    __nv_bfloat162 ph0 = __halves2bfloat162(h0, h1), ph1 = __halves2bfloat162(h2, h3);
    __nv_bfloat162 pl0 = __halves2bfloat162(__float2bfloat16(v.x - __bfloat162float(h0)),
                                            __float2bfloat16(v.y - __bfloat162float(h1)));
    __nv_bfloat162 pl1 = __halves2bfloat162(__float2bfloat16(v.z - __bfloat162float(h2)),
                                            __float2bfloat16(v.w - __bfloat162float(h3)));
    *(__nv_bfloat162*)(hi + (size_t)idx * 4)     = ph0;
    *(__nv_bfloat162*)(hi + (size_t)idx * 4 + 2) = ph1;
    *(__nv_bfloat162*)(lo + (size_t)idx * 4)     = pl0;
    *(__nv_bfloat162*)(lo + (size_t)idx * 4 + 2) = pl1;
}

// masked split for h_seq (rows of length U_)
__global__ void convert_mask(const float* __restrict__ hseq,
                             const float* __restrict__ mask,
                             __nv_bfloat16* __restrict__ hi,
                             __nv_bfloat16* __restrict__ lo, int n4) {
    int idx = blockIdx.x * blockDim.x + threadIdx.x;
    if (idx >= n4) return;
    float m = mask[(idx * 4) >> 9];   // U_ = 512
    float4 v = *(const float4*)(hseq + (size_t)idx * 4);
    v.x *= m; v.y *= m; v.z *= m; v.w *= m;
    __nv_bfloat16 h0 = __float2bfloat16(v.x), h1 = __float2bfloat16(v.y);
    __nv_bfloat16 h2 = __float2bfloat16(v.z), h3 = __float2bfloat16(v.w);
    *(__nv_bfloat162*)(hi + (size_t)idx * 4)     = __halves2bfloat162(h0, h1);
    *(__nv_bfloat162*)(hi + (size_t)idx * 4 + 2) = __halves2bfloat162(h2, h3);
    *(__nv_bfloat162*)(lo + (size_t)idx * 4)     =
        __halves2bfloat162(__float2bfloat16(v.x - __bfloat162float(h0)),
                           __float2bfloat16(v.y - __bfloat162float(h1)));
    *(__nv_bfloat162*)(lo + (size_t)idx * 4 + 2) =
        __halves2bfloat162(__float2bfloat16(v.z - __bfloat162float(h2)),
                           __float2bfloat16(v.w - __bfloat162float(h3)));
}

__global__ void init_kernel(const float* __restrict__ b_lstm,
                            float* __restrict__ b4,
                            float* __restrict__ h0,
                            unsigned* __restrict__ bar) {
    int idx = blockIdx.x * blockDim.x + threadIdx.x;
    if (idx == 0) *bar = 0u;
    if (idx < G4_) b4[idx] = b_lstm[(idx & 3) * U_ + (idx >> 2)];
    if (idx < B_ * U_) h0[idx] = 0.0f;
}

// ---------------------------------------------------------------------------
// Tensor-core GEMM on pre-split bf16 hi/lo operands (3-term 3xBF16).
// C[M,N] = A @ B + bias, optional relu. 128x128x32 tiles, 8 warps (4x2),
// cp.async double-buffered SMEM, ldmatrix, mma.m16n8k16.
// __launch_bounds__(256, 2): cap regs at 128 -> 2 CTAs/SM (reg-file was the
// occupancy limiter at regs=170; SMEM 2x75776 fits the 228KB carveout).
// ---------------------------------------------------------------------------
__global__ __launch_bounds__(256, 2) void tgemm2(
    const __nv_bfloat16* __restrict__ Ah, const __nv_bfloat16* __restrict__ Al,
    const __nv_bfloat16* __restrict__ Bh, const __nv_bfloat16* __restrict__ Bl,
    const float* __restrict__ bias, float* __restrict__ C,
    int M, int N, int K, int relu)
{
    extern __shared__ __nv_bfloat16 ts[];

    int tid  = threadIdx.x;
    int warp = tid >> 5, lane = tid & 31;
    int wm = warp >> 1, wn = warp & 1;
    int m0 = blockIdx.y * 128, n0 = blockIdx.x * 128;

    // loader chunk ids: c1=tid, c2=tid+256 (16B each)
    int a1r = tid >> 2,         a1s = tid & 3;
    int a2r = (tid + 256) >> 2, a2s = (tid + 256) & 3;
    int b1r = tid >> 4,         b1s = tid & 15;
    int b2r = (tid + 256) >> 4, b2s = (tid + 256) & 15;

    float acc[2][8][4];
    #pragma unroll
    for (int i = 0; i < 2; i++)
        #pragma unroll
        for (int j = 0; j < 8; j++)
            #pragma unroll
            for (int q = 0; q < 4; q++) acc[i][j][q] = 0.0f;

    // per-lane ldmatrix offsets (element units within each matrix tile)
    int a_r = (lane & 15);
    int a_c = (lane >> 4) * 8;
    int aoffA = (wm * 32 + a_r) * APITCH + a_c;
    int aoffB = a_r * BPITCH + wn * 64 + a_c;

    int KT = K / BKT;

    auto load_stage = [&](int kt, int s) {
        __nv_bfloat16* st = ts + s * STAGE_ELEM;
        __nv_bfloat16* sAh = st;
        __nv_bfloat16* sAl = st + SA_ELEM;
        __nv_bfloat16* sBh = st + 2 * SA_ELEM;
        __nv_bfloat16* sBl = st + 2 * SA_ELEM + SB_ELEM;
        int k0 = kt * BKT;
        const __nv_bfloat16* gAh = Ah + (size_t)m0 * K + k0;
        const __nv_bfloat16* gAl = Al + (size_t)m0 * K + k0;
        const __nv_bfloat16* gBh = Bh + (size_t)k0 * N + n0;
        const __nv_bfloat16* gBl = Bl + (size_t)k0 * N + n0;
        cpa16(smem_u32(sAh + a1r * APITCH + a1s * 8), gAh + (size_t)a1r * K + a1s * 8);
        cpa16(smem_u32(sAh + a2r * APITCH + a2s * 8), gAh + (size_t)a2r * K + a2s * 8);
        cpa16(smem_u32(sAl + a1r * APITCH + a1s * 8), gAl + (size_t)a1r * K + a1s * 8);
        cpa16(smem_u32(sAl + a2r * APITCH + a2s * 8), gAl + (size_t)a2r * K + a2s * 8);
        cpa16(smem_u32(sBh + b1r * BPITCH + b1s * 8), gBh + (size_t)b1r * N + b1s * 8);
        cpa16(smem_u32(sBh + b2r * BPITCH + b2s * 8), gBh + (size_t)b2r * N + b2s * 8);
        cpa16(smem_u32(sBl + b1r * BPITCH + b1s * 8), gBl + (size_t)b1r * N + b1s * 8);
        cpa16(smem_u32(sBl + b2r * BPITCH + b2s * 8), gBl + (size_t)b2r * N + b2s * 8);
    };

    load_stage(0, 0);
    cpa_commit();
    cpa_wait0();
    __syncthreads();

    for (int kt = 0; kt < KT; kt++) {
        int cur = kt & 1;
        if (kt + 1 < KT) {
            load_stage(kt + 1, cur ^ 1);
            cpa_commit();
        }

        __nv_bfloat16* st = ts + cur * STAGE_ELEM;
        uint32_t aAh = smem_u32(st + aoffA);
        uint32_t aAl = smem_u32(st + SA_ELEM + aoffA);
        uint32_t aBh = smem_u32(st + 2 * SA_ELEM + aoffB);
        uint32_t aBl = smem_u32(st + 2 * SA_ELEM + SB_ELEM + aoffB);

        #pragma unroll
        for (int kk = 0; kk < 2; kk++) {
            uint32_t Ahf[2][4], Alf[2][4];
            #pragma unroll
            for (int mt = 0; mt < 2; mt++) {
                uint32_t off = (mt * 16) * APITCH * 2 + kk * 16 * 2;   // bytes
                ldsm_x4(Ahf[mt][0], Ahf[mt][1], Ahf[mt][2], Ahf[mt][3], aAh + off);
                ldsm_x4(Alf[mt][0], Alf[mt][1], Alf[mt][2], Alf[mt][3], aAl + off);
            }
            uint32_t Bhf[8][2], Blf[8][2];
            #pragma unroll
            for (int p = 0; p < 4; p++) {
                uint32_t off = (kk * 16) * BPITCH * 2 + p * 16 * 2;    // bytes
                ldsm_x4t(Bhf[2*p][0], Bhf[2*p][1], Bhf[2*p+1][0], Bhf[2*p+1][1], aBh + off);
                ldsm_x4t(Blf[2*p][0], Blf[2*p][1], Blf[2*p+1][0], Blf[2*p+1][1], aBl + off);
            }
            #pragma unroll
            for (int mt = 0; mt < 2; mt++)
                #pragma unroll
                for (int nt = 0; nt < 8; nt++) {
                    mma_bf16(acc[mt][nt], Ahf[mt], Bhf[nt]);
                    mma_bf16(acc[mt][nt], Ahf[mt], Blf[nt]);
                    mma_bf16(acc[mt][nt], Alf[mt], Bhf[nt]);
                }
        }

        if (kt + 1 < KT) cpa_wait0();
        __syncthreads();
    }

    // Epilogue
    int crow = lane >> 2;
    int ccol = (lane & 3) * 2;
    #pragma unroll
    for (int mt = 0; mt < 2; mt++) {
        int r0 = m0 + wm * 32 + mt * 16 + crow;
        #pragma unroll
        for (int nt = 0; nt < 8; nt++) {
            int cglob = n0 + wn * 64 + nt * 8 + ccol;
            float b0 = bias[cglob], b1 = bias[cglob + 1];
            float2 v0 = { acc[mt][nt][0] + b0, acc[mt][nt][1] + b1 };
            float2 v1 = { acc[mt][nt][2] + b0, acc[mt][nt][3] + b1 };
            if (relu) {
                v0.x = fmaxf(v0.x, 0.f); v0.y = fmaxf(v0.y, 0.f);
                v1.x = fmaxf(v1.x, 0.f); v1.y = fmaxf(v1.y, 0.f);
            }
            *(float2*)(C + (size_t)r0 * N + cglob)       = v0;
            *(float2*)(C + (size_t)(r0 + 8) * N + cglob) = v1;
        }
    }
}

// ---------------------------------------------------------------------------
// Persistent LSTM recurrence (unchanged; known good).
// ---------------------------------------------------------------------------
__global__ __launch_bounds__(256) void lstm_persistent(
    const float* __restrict__ h0,
    const float* __restrict__ xz,
    const float* __restrict__ Wrec,
    float* hseq,
    unsigned* bar)
{
    extern __shared__ float smemf[];
    float* Ws = smemf;                // [512][16]
    float* Hs = smemf + 512 * 16;     // [KC][129]

    int tid = threadIdx.x;
    int blk = blockIdx.x;
    int n0 = blk * 16;
    int tx = tid & 3;
    int ty = tid >> 2;
    int u  = blk * 4 + tx;

    for (int l = tid; l < 512 * 4; l += 256) {
        int row = l >> 2, c4 = l & 3;
        *(float4*)&Ws[row * 16 + c4 * 4] =
            *(const float4*)(Wrec + (size_t)row * G4_ + n0 + c4 * 4);
    }

    float creg0 = 0.0f, creg1 = 0.0f;
    const float* hp = h0;

    for (int t = 0; t < T_; t++) {
        float acc[2][4];
        #pragma unroll
        for (int i = 0; i < 2; i++)
            #pragma unroll
            for (int j = 0; j < 4; j++) acc[i][j] = 0.0f;

        for (int k0 = 0; k0 < U_; k0 += KC) {
            #pragma unroll
            for (int i = 0; i < 4; i++) {
                int l = tid + i * 256;
                int b = l >> 3, k4 = l & 7;
                float4 v = __ldcg((const float4*)(hp + (size_t)b * U_ + k0 + k4 * 4));
                Hs[(k4 * 4 + 0) * 129 + b] = v.x;
                Hs[(k4 * 4 + 1) * 129 + b] = v.y;
                Hs[(k4 * 4 + 2) * 129 + b] = v.z;
                Hs[(k4 * 4 + 3) * 129 + b] = v.w;
            }
            __syncthreads();

            #pragma unroll
            for (int kk = 0; kk < KC; kk++) {
                float4 wv = *(float4*)&Ws[(k0 + kk) * 16 + tx * 4];
                float ha = Hs[kk * 129 + ty * 2 + 0];
                float hb = Hs[kk * 129 + ty * 2 + 1];
                acc[0][0] += ha * wv.x; acc[0][1] += ha * wv.y;
                acc[0][2] += ha * wv.z; acc[0][3] += ha * wv.w;
                acc[1][0] += hb * wv.x; acc[1][1] += hb * wv.y;
                acc[1][2] += hb * wv.z; acc[1][3] += hb * wv.w;
            }
            __syncthreads();
        }

        #pragma unroll
        for (int i = 0; i < 2; i++) {
            int b = ty * 2 + i;
            const float* xzp = xz + ((size_t)t * B_ + b) * G4_ + n0 + tx * 4;
            float zi = acc[i][0] + xzp[0];
            float zf = acc[i][1] + xzp[1];
            float zg = acc[i][2] + xzp[2];
            float zo = acc[i][3] + xzp[3];
            float ig = 1.0f / (1.0f + expf(-zi));
            float fg = 1.0f / (1.0f + expf(-zf));
            float gg = tanhf(zg);
            float og = 1.0f / (1.0f + expf(-zo));
            float cp = i ? creg1 : creg0;
            float cn = fg * cp + ig * gg;
            if (i) creg1 = cn; else creg0 = cn;
            hseq[((size_t)t * B_ + b) * U_ + u] = og * tanhf(cn);
        }

        __threadfence();
        __syncthreads();
        if (tid == 0) {
            atomicAdd(bar, 1u);
            unsigned target = (unsigned)RBLK * (unsigned)(t + 1);
            while (*(volatile unsigned*)bar < target) {}
        }
        __syncthreads();

        hp = hseq + (size_t)t * B_ * U_;
    }
}

// ---------------------------------------------------------------------------
// In-place row softmax (1024 cols, one block/row).
// ---------------------------------------------------------------------------
__global__ __launch_bounds__(256) void softmax_kernel(float* __restrict__ out) {
    __shared__ float red[8];
    int tid = threadIdx.x;
    float* p = out + (size_t)blockIdx.x * CODES_;

    float4 v = *(float4*)(p + tid * 4);
    float m = fmaxf(fmaxf(v.x, v.y), fmaxf(v.z, v.w));
    #pragma unroll
    for (int o = 16; o > 0; o >>= 1) m = fmaxf(m, __shfl_xor_sync(0xFFFFFFFFu, m, o));
    if ((tid & 31) == 0) red[tid >> 5] = m;
    __syncthreads();
    float bm = red[0];
    #pragma unroll
    for (int i = 1; i < 8; i++) bm = fmaxf(bm, red[i]);
    __syncthreads();

    v.x = expf(v.x - bm); v.y = expf(v.y - bm);
    v.z = expf(v.z - bm); v.w = expf(v.w - bm);
    float s = v.x + v.y + v.z + v.w;
    #pragma unroll
    for (int o = 16; o > 0; o >>= 1) s += __shfl_xor_sync(0xFFFFFFFFu, s, o);
    if ((tid & 31) == 0) red[tid >> 5] = s;
    __syncthreads();
    float bs = red[0];
    #pragma unroll
    for (int i = 1; i < 8; i++) bs += red[i];
    float inv = 1.0f / bs;
    v.x *= inv; v.y *= inv; v.z *= inv; v.w *= inv;
    *(float4*)(p + tid * 4) = v;
}

// ---------------------------------------------------------------------------
// Launch
// ---------------------------------------------------------------------------
extern "C" void kernel_launch(void* const* d_in, const int* in_sizes, int n_in,
                              void* d_out, int out_size) {
    const float* x       = (const float*)d_in[0];
    const float* mask    = (const float*)d_in[1];
    const float* W_in    = (const float*)d_in[2];
    const float* W_rec   = (const float*)d_in[3];
    const float* b_lstm  = (const float*)d_in[4];
    const float* W_dense = (const float*)d_in[5];
    const float* b_dense = (const float*)d_in[6];
    float* out = (float*)d_out;

    float *xz, *hseq, *h0, *Wrec4, *b4;
    unsigned* bar;
    __nv_bfloat16 *xh, *xl, *Wih, *Wil, *Wdh, *Wdl, *hh, *hl;
    cudaGetSymbolAddress((void**)&xz,    g_xz);
    cudaGetSymbolAddress((void**)&hseq,  g_hseq);
    cudaGetSymbolAddress((void**)&h0,    g_h0);
    cudaGetSymbolAddress((void**)&Wrec4, g_Wrec4);
    cudaGetSymbolAddress((void**)&b4,    g_b4);
    cudaGetSymbolAddress((void**)&bar,   g_bar);
    cudaGetSymbolAddress((void**)&xh,    g_xh);
    cudaGetSymbolAddress((void**)&xl,    g_xl);
    cudaGetSymbolAddress((void**)&Wih,   g_Wih);
    cudaGetSymbolAddress((void**)&Wil,   g_Wil);
    cudaGetSymbolAddress((void**)&Wdh,   g_Wdh);
    cudaGetSymbolAddress((void**)&Wdl,   g_Wdl);
    cudaGetSymbolAddress((void**)&hh,    g_hh);
    cudaGetSymbolAddress((void**)&hl,    g_hl);

    int lstm_smem = (512 * 16 + KC * 129) * (int)sizeof(float);
    cudaFuncSetAttribute(lstm_persistent,
                         cudaFuncAttributeMaxDynamicSharedMemorySize, lstm_smem);
    cudaFuncSetAttribute(tgemm2,
                         cudaFuncAttributeMaxDynamicSharedMemorySize, GEMM_SMEM);

    // Pre-passes
    reorder_gates<<<(U_ * G4_ + 255) / 256, 256>>>(W_rec, Wrec4, U_ * G4_);
    reorder_split<<<(F_ * G4_ + 255) / 256, 256>>>(W_in, Wih, Wil, F_ * G4_);
    convert_split<<<(U_ * CODES_ / 4 + 255) / 256, 256>>>(W_dense, Wdh, Wdl, U_ * CODES_ / 4);
    convert_split<<<((int)((size_t)ROWS_ * F_ / 4) + 255) / 256, 256>>>(x, xh, xl, (int)((size_t)ROWS_ * F_ / 4));
    init_kernel<<<(B_ * U_ + 255) / 256, 256>>>(b_lstm, b4, h0, bar);

    // Phase 1: xz = x @ Win4 + b4 (tensor, pre-split operands)
    tgemm2<<<dim3(G4_ / 128, ROWS_ / 128), 256, GEMM_SMEM>>>(
        xh, xl, Wih, Wil, b4, xz, ROWS_, G4_, F_, 0);

    // Phase 2: persistent recurrence
    lstm_persistent<<<RBLK, 256, lstm_smem>>>(h0, xz, Wrec4, hseq, bar);

    // Phase 2.5: masked h -> bf16 hi/lo
    convert_mask<<<((int)((size_t)ROWS_ * U_ / 4) + 255) / 256, 256>>>(
        hseq, mask, hh, hl, (int)((size_t)ROWS_ * U_ / 4));

    // Phase 3: logits = relu(masked_h @ W_dense + b_dense)
    tgemm2<<<dim3(CODES_ / 128, ROWS_ / 128), 256, GEMM_SMEM>>>(
        hh, hl, Wdh, Wdl, b_dense, out, ROWS_, CODES_, U_, 1);

    // Phase 4: softmax
    softmax_kernel<<<ROWS_, 256>>>(out);
}